// round 4
// baseline (speedup 1.0000x reference)
#include <cuda_runtime.h>
#include <cstdint>

// Problem constants
#define Bsz 4
#define Nn  1024
#define Ff  256
#define NW  32          // 1024 bits -> 32 u32 words per row
#define FULL 0xFFFFFFFFu

// Output layout (float32, tuple flattened): x_p [B,N,F], pos_p [B,N,3], a [B,N,N], mask [B,N]
#define OFF_XP   0
#define OFF_POS  (Bsz*Nn*Ff)                 // 1048576
#define OFF_A    (OFF_POS + Bsz*Nn*3)        // 1060864
#define OFF_MASK (OFF_A + Bsz*Nn*Nn)         // 5255168

// Scratch (device globals; no allocations allowed)
__device__ uint32_t g_bits[Bsz*Nn*NW];   // A != 0 bitmask rows
__device__ uint2    g_comb[Bsz*Nn*NW];   // {bits word, inc word} fused: one LDG.64 per lane
__device__ int      g_perm[Bsz*Nn];
__device__ int      g_K[Bsz];

// ---------------------------------------------------------------------------
// Zero the x_p / pos_p / a regions (mask region is fully written by k_select)
__global__ void k_zero(float4* __restrict__ p, int n4) {
    int i = blockIdx.x * blockDim.x + threadIdx.x;
    int stride = gridDim.x * blockDim.x;
    float4 z = make_float4(0.f, 0.f, 0.f, 0.f);
    for (; i < n4; i += stride) p[i] = z;
}

// ---------------------------------------------------------------------------
// Build adjacency bitmasks: one warp per 32-bit word. Coalesced 16MB read.
__global__ void k_bits(const float* __restrict__ adj) {
    int wid  = (blockIdx.x * blockDim.x + threadIdx.x) >> 5;  // [0, B*N*NW)
    int lane = threadIdx.x & 31;
    int w    = wid & 31;
    int row  = wid >> 5;           // b*N + i
    float v  = adj[(size_t)row * Nn + w * 32 + lane];
    uint32_t bits = __ballot_sync(FULL, v != 0.0f);
    if (lane == 0) g_bits[row * NW + w] = bits;
}

// ---------------------------------------------------------------------------
// inc_row(i) = (A^2 + A)[i] != 0 = union of neighbor rows | own row.
// One warp per node row; lane owns one word. Writes fused {bits, inc} words.
__global__ void k_inc() {
    int wid  = (blockIdx.x * blockDim.x + threadIdx.x) >> 5;
    int lane = threadIdx.x & 31;
    if (wid >= Bsz * Nn) return;
    int b = wid >> 10;
    int rowbase = wid * NW;
    uint32_t myw = g_bits[rowbase + lane];
    uint32_t acc = myw;
    for (int w = 0; w < NW; ++w) {
        uint32_t mw = __shfl_sync(FULL, myw, w);
        while (mw) {
            int j = __ffs(mw) - 1; mw &= mw - 1;
            int k = w * 32 + j;
            acc |= g_bits[(b * Nn + k) * NW + lane];
        }
    }
    g_comb[rowbase + lane] = make_uint2(myw, acc);
}

// ---------------------------------------------------------------------------
// Fast warp argmin over 1024 values with mask, first-occurrence tie-break.
// In-lane: contiguous-block pairwise tree (left block always has smaller
// indices, so <= preserves first-occurrence). Cross-lane: butterfly shfl_xor
// with explicit (value, index) lexicographic compare -> all lanes converge.
#define INF32 __int_as_float(0x7f800000)

__device__ __forceinline__ void argmin32(uint32_t m, const float ord[32], int lane,
                                         float& obv, int& obi) {
    float v[32]; int ix[32];
#pragma unroll
    for (int j = 0; j < 32; ++j)
        v[j] = ((m >> j) & 1u) ? ord[j] : INF32;
#pragma unroll
    for (int k = 0; k < 32; k += 2) {
        bool c = v[k] <= v[k + 1];
        ix[k] = c ? k : (k + 1);
        v[k]  = c ? v[k] : v[k + 1];
    }
#pragma unroll
    for (int k = 0; k < 32; k += 4) {
        bool c = v[k] <= v[k + 2];
        ix[k] = c ? ix[k] : ix[k + 2];
        v[k]  = c ? v[k] : v[k + 2];
    }
#pragma unroll
    for (int k = 0; k < 32; k += 8) {
        bool c = v[k] <= v[k + 4];
        ix[k] = c ? ix[k] : ix[k + 4];
        v[k]  = c ? v[k] : v[k + 4];
    }
#pragma unroll
    for (int k = 0; k < 32; k += 16) {
        bool c = v[k] <= v[k + 8];
        ix[k] = c ? ix[k] : ix[k + 8];
        v[k]  = c ? v[k] : v[k + 8];
    }
    {
        bool c = v[0] <= v[16];
        ix[0] = c ? ix[0] : ix[16];
        v[0]  = c ? v[0] : v[16];
    }
    float bv = v[0];
    int   bi = lane * 32 + ix[0];
#pragma unroll
    for (int off = 16; off; off >>= 1) {
        float ov = __shfl_xor_sync(FULL, bv, off);
        int   oi = __shfl_xor_sync(FULL, bi, off);
        if (ov < bv || (ov == bv && oi < bi)) { bv = ov; bi = oi; }
    }
    obv = bv; obi = bi;
}

// ---------------------------------------------------------------------------
// Sequential greedy frontier selection (K-MIS stride 2), one warp per batch.
// Exactly mirrors the JAX while_loop semantics (incl. frontier-restart rule
// and argmin first-index tie-break). Also builds perm (stable top_k of 0/1)
// and writes the mask output.
__global__ void __launch_bounds__(32, 1)
k_select(const float* __restrict__ order, float* __restrict__ out_mask) {
    int b = blockIdx.x;
    int lane = threadIdx.x;
    const float* ob = order + b * Nn;

    // cache this lane's 32 order values in registers (nodes lane*32 .. +31)
    float ord[32];
#pragma unroll
    for (int j = 0; j < 32; ++j) ord[j] = ob[lane * 32 + j];

    const uint2* comb = g_comb + b * Nn * NW;

    uint32_t av = FULL, sel = 0u, fr = 0u;

    // idx0 = argmin over all nodes
    float bv; int bi;
    argmin32(FULL, ord, lane, bv, bi);
    int idx = bi;

    fr = (lane == (idx >> 5)) ? (1u << (idx & 31)) : 0u;
    bool fr_any = true;

    while (__ballot_sync(FULL, av != 0u)) {
        uint32_t cur = (lane == (idx >> 5)) ? (1u << (idx & 31)) : 0u;
        sel |= cur;
        uint2 rw = comb[idx * NW + lane];           // {adj1 row word, adj2 row word}
        av &= ~(rw.x | cur);                        // remove current + excluded
        uint32_t frn = fr_any ? (fr | rw.y) : FULL; // restart if old frontier empty
        fr = frn & av;

        argmin32(fr, ord, lane, bv, bi);
        fr_any = (bv < INF32);                      // frontier empty <=> min == INF
        if (fr_any) idx = bi;
    }

    // Stable top_k of 0/1 floats == selected indices ascending, then unselected.
    int cnt = __popc(sel);
    int incl = cnt;
    for (int off = 1; off < 32; off <<= 1) {
        int v = __shfl_up_sync(FULL, incl, off);
        if (lane >= off) incl += v;
    }
    int excl = incl - cnt;
    int K = __shfl_sync(FULL, incl, 31);

    uint32_t s = sel; int r = 0;
    while (s) { int j = __ffs(s) - 1; s &= s - 1; g_perm[b * Nn + excl + r] = lane * 32 + j; ++r; }
    int excl_u = lane * 32 - excl;
    s = ~sel; r = 0;
    while (s) { int j = __ffs(s) - 1; s &= s - 1; g_perm[b * Nn + K + excl_u + r] = lane * 32 + j; ++r; }

    if (lane == 0) g_K[b] = K;
    for (int t = lane; t < Nn; t += 32)
        out_mask[b * Nn + t] = (t < K) ? 1.0f : 0.0f;
}

// ---------------------------------------------------------------------------
// x_p[b,k,f] = sum_{n in N(j)} x[b,n,f] + x[b,j,f], j = perm[b,k], k < K.
// One block (256 threads = F columns) per (b,k). Non-selected rows stay zero.
__global__ void k_xp(const float* __restrict__ x, float* __restrict__ out_xp) {
    int b = blockIdx.y, k = blockIdx.x;
    if (k >= g_K[b]) return;
    int j = g_perm[b * Nn + k];
    __shared__ uint32_t sh[NW];
    if (threadIdx.x < NW) sh[threadIdx.x] = g_bits[(b * Nn + j) * NW + threadIdx.x];
    __syncthreads();
    int f = threadIdx.x;
    const float* xb = x + (size_t)b * Nn * Ff;
    float acc = xb[(size_t)j * Ff + f];
    for (int w = 0; w < NW; ++w) {
        uint32_t m = sh[w];
        while (m) {
            int n = w * 32 + __ffs(m) - 1; m &= m - 1;
            acc += xb[(size_t)n * Ff + f];
        }
    }
    out_xp[((size_t)(b * Nn) + k) * Ff + f] = acc;
}

// ---------------------------------------------------------------------------
// pos_p[b,k,:] = (sum_{n in N(j)} pos[n] + pos[j]) / (deg(j)+1). Warp per (b,k).
__global__ void k_pos(const float* __restrict__ pos, float* __restrict__ out_pos) {
    int wid  = (blockIdx.x * blockDim.x + threadIdx.x) >> 5;
    int lane = threadIdx.x & 31;
    if (wid >= Bsz * Nn) return;
    int b = wid >> 10, k = wid & (Nn - 1);
    if (k >= g_K[b]) return;
    int j = g_perm[b * Nn + k];
    uint32_t m = g_bits[(b * Nn + j) * NW + lane];
    const float* pb = pos + (size_t)b * Nn * 3;
    float sx = 0.f, sy = 0.f, sz = 0.f;
    int c = __popc(m);
    while (m) {
        int n = lane * 32 + __ffs(m) - 1; m &= m - 1;
        sx += pb[n * 3 + 0]; sy += pb[n * 3 + 1]; sz += pb[n * 3 + 2];
    }
    for (int off = 16; off; off >>= 1) {
        sx += __shfl_down_sync(FULL, sx, off);
        sy += __shfl_down_sync(FULL, sy, off);
        sz += __shfl_down_sync(FULL, sz, off);
        c  += __shfl_down_sync(FULL, c,  off);
    }
    if (lane == 0) {
        float deg = (float)(c + 1);
        out_pos[(b * Nn + k) * 3 + 0] = (sx + pb[j * 3 + 0]) / deg;
        out_pos[(b * Nn + k) * 3 + 1] = (sy + pb[j * 3 + 1]) / deg;
        out_pos[(b * Nn + k) * 3 + 2] = (sz + pb[j * 3 + 2]) / deg;
    }
}

// ---------------------------------------------------------------------------
// a[b,k1,k2] = popc(bits_{p1} & bits_{p2}) + A[p1,p2]   (k1,k2 < K), else 0.
// One block per (b,k1); bits_{p1} in shared; thread per k2.
__global__ void k_a(const float* __restrict__ adj, float* __restrict__ out_a) {
    int b = blockIdx.y, k1 = blockIdx.x;
    if (k1 >= g_K[b]) return;
    int p1 = g_perm[b * Nn + k1];
    __shared__ uint32_t sh[NW];
    if (threadIdx.x < NW) sh[threadIdx.x] = g_bits[(b * Nn + p1) * NW + threadIdx.x];
    __syncthreads();
    int Kc = g_K[b];
    const float* ab = adj + (size_t)(b * Nn + p1) * Nn;
    for (int k2 = threadIdx.x; k2 < Kc; k2 += blockDim.x) {
        int p2 = g_perm[b * Nn + k2];
        int c = 0;
#pragma unroll
        for (int w = 0; w < NW; ++w)
            c += __popc(sh[w] & g_bits[(b * Nn + p2) * NW + w]);
        out_a[((size_t)(b * Nn) + k1) * Nn + k2] = (float)c + ab[p2];
    }
}

// ---------------------------------------------------------------------------
extern "C" void kernel_launch(void* const* d_in, const int* in_sizes, int n_in,
                              void* d_out, int out_size) {
    const float* x     = (const float*)d_in[0];
    const float* adj   = (const float*)d_in[1];
    const float* pos   = (const float*)d_in[2];
    const float* order = (const float*)d_in[3];
    float* out = (float*)d_out;

    // zero x_p / pos_p / a regions (OFF_MASK floats, 16B aligned & divisible by 4)
    k_zero<<<2048, 256>>>((float4*)out, OFF_MASK / 4);
    // adjacency bitmasks: B*N*NW warps
    k_bits<<<(Bsz * Nn * NW * 32) / 256, 256>>>(adj);
    // 2-hop reach bitmasks + fused {bits,inc} words: B*N warps
    k_inc<<<(Bsz * Nn * 32) / 256, 256>>>();
    // sequential selection, perm, mask
    k_select<<<Bsz, 32>>>(order, out + OFF_MASK);
    // pooled outputs
    k_xp<<<dim3(Nn, Bsz), 256>>>(x, out + OFF_XP);
    k_pos<<<(Bsz * Nn * 32) / 256, 256>>>(pos, out + OFF_POS);
    k_a<<<dim3(Nn, Bsz), 256>>>(adj, out + OFF_A);
}

// round 5
// speedup vs baseline: 1.0780x; 1.0780x over previous
#include <cuda_runtime.h>
#include <cstdint>

// Problem constants
#define Bsz 4
#define Nn  1024
#define Ff  256
#define NW  32          // 1024 bits -> 32 u32 words per row
#define FULL 0xFFFFFFFFu

// Output layout (float32, tuple flattened): x_p [B,N,F], pos_p [B,N,3], a [B,N,N], mask [B,N]
#define OFF_XP   0
#define OFF_POS  (Bsz*Nn*Ff)                 // 1048576
#define OFF_A    (OFF_POS + Bsz*Nn*3)        // 1060864
#define OFF_MASK (OFF_A + Bsz*Nn*Nn)         // 5255168

// Scratch (device globals; no allocations allowed)
__device__ uint32_t g_bits0[Bsz*Nn*NW];  // A != 0, ORIGINAL node space (for pooling kernels)
__device__ uint32_t g_bitsR[Bsz*Nn*NW];  // A != 0, RANK space (rows & cols relabeled by order rank)
__device__ uint2    g_comb [Bsz*Nn*NW];  // rank space {adj1 word, adj2 word} fused rows
__device__ int      g_nodeof[Bsz*Nn];    // nodeof[b][rank] = original node id
__device__ int      g_perm[Bsz*Nn];
__device__ int      g_K[Bsz];

// ---------------------------------------------------------------------------
// Build adjacency bitmasks (original space): one warp per 32-bit word.
__global__ void k_bits(const float* __restrict__ adj) {
    int wid  = (blockIdx.x * blockDim.x + threadIdx.x) >> 5;  // [0, B*N*NW)
    int lane = threadIdx.x & 31;
    int w    = wid & 31;
    int row  = wid >> 5;           // b*N + i
    float v  = adj[(size_t)row * Nn + w * 32 + lane];
    uint32_t bits = __ballot_sync(FULL, v != 0.0f);
    if (lane == 0) g_bits0[row * NW + w] = bits;
}

// ---------------------------------------------------------------------------
// Rank nodes by (order, index) ascending. nodeof[b][rank] = node.
// order in [0,1) -> float bits are monotone as uint; key = (bits<<10)|idx.
// grid (Bsz, 8), block 128: block handles 128 nodes, counts over all 1024.
__global__ void k_rank(const float* __restrict__ order) {
    __shared__ unsigned long long keys[Nn];
    int b = blockIdx.x, part = blockIdx.y, t = threadIdx.x;
    for (int j = t; j < Nn; j += 128)
        keys[j] = ((unsigned long long)__float_as_uint(order[b * Nn + j]) << 10) | (unsigned)j;
    __syncthreads();
    int i = part * 128 + t;
    unsigned long long ki = keys[i];
    int rk = 0;
#pragma unroll 8
    for (int j = 0; j < Nn; ++j) rk += (keys[j] < ki);
    g_nodeof[b * Nn + rk] = i;
}

// ---------------------------------------------------------------------------
// Permute bitmasks into rank space: row r = row nodeof[r], column bit j of
// word w = column nodeof[w*32+j]. One warp per output row; row cached in smem,
// lane builds output word `lane` from register-resident column map.
__global__ void k_permute() {
    __shared__ uint32_t sm[8][NW];
    int wid  = (blockIdx.x * blockDim.x + threadIdx.x) >> 5;  // b*Nn + r
    int lane = threadIdx.x & 31;
    int wb   = (threadIdx.x >> 5) & 7;
    if (wid >= Bsz * Nn) return;
    int b = wid >> 10;
    int nid = g_nodeof[wid];
    sm[wb][lane] = g_bits0[(b * Nn + nid) * NW + lane];
    __syncwarp();
    // output word `lane` covers ranks lane*32 .. lane*32+31
    const int4* nf = (const int4*)(g_nodeof + (b << 10) + (lane << 5));
    uint32_t out = 0;
#pragma unroll
    for (int q = 0; q < 8; ++q) {
        int4 nc = nf[q];
        out |= ((sm[wb][nc.x >> 5] >> (nc.x & 31)) & 1u) << (q * 4 + 0);
        out |= ((sm[wb][nc.y >> 5] >> (nc.y & 31)) & 1u) << (q * 4 + 1);
        out |= ((sm[wb][nc.z >> 5] >> (nc.z & 31)) & 1u) << (q * 4 + 2);
        out |= ((sm[wb][nc.w >> 5] >> (nc.w & 31)) & 1u) << (q * 4 + 3);
    }
    g_bitsR[wid * NW + lane] = out;
}

// ---------------------------------------------------------------------------
// inc_row(r) = (A^2 + A)[r] != 0, rank space. One warp per rank row.
// Writes fused {adj1 word, adj2 word}.
__global__ void k_inc() {
    int wid  = (blockIdx.x * blockDim.x + threadIdx.x) >> 5;
    int lane = threadIdx.x & 31;
    if (wid >= Bsz * Nn) return;
    int b = wid >> 10;
    int rowbase = wid * NW;
    uint32_t myw = g_bitsR[rowbase + lane];
    uint32_t acc = myw;
    for (int w = 0; w < NW; ++w) {
        uint32_t mw = __shfl_sync(FULL, myw, w);
        while (mw) {
            int j = __ffs(mw) - 1; mw &= mw - 1;
            int k = w * 32 + j;                       // neighbor rank
            acc |= g_bitsR[(b * Nn + k) * NW + lane];
        }
    }
    g_comb[rowbase + lane] = make_uint2(myw, acc);
}

// ---------------------------------------------------------------------------
// Sequential greedy frontier selection, one warp per batch, ALL IN RANK SPACE.
// argmin(order over frontier) == lowest set bit of frontier mask (rank order
// is ascending order value, ties broken by index -> exact JAX argmin).
__global__ void __launch_bounds__(32, 1)
k_select(float* __restrict__ out_mask) {
    int b = blockIdx.x;
    int lane = threadIdx.x;
    const uint2* comb = g_comb + b * Nn * NW;
    const int* nodeof = g_nodeof + b * Nn;

    uint32_t av = FULL, selR = 0u, selO = 0u, fr;
    int idx = 0;                            // rank 0 = global argmin
    fr = (lane == 0) ? 1u : 0u;
    bool fr_any = true;

    while (__ballot_sync(FULL, av != 0u)) {
        uint32_t cur = (lane == (idx >> 5)) ? (1u << (idx & 31)) : 0u;
        selR |= cur;
        int nid = nodeof[idx];              // off the critical path
        uint32_t curO = (lane == (nid >> 5)) ? (1u << (nid & 31)) : 0u;
        selO |= curO;

        uint2 rw = comb[idx * NW + lane];   // {adj1 row word, adj2 row word}
        av &= ~(rw.x | cur);
        uint32_t frn = fr_any ? (fr | rw.y) : FULL;   // restart if frontier was empty
        fr = frn & av;

        uint32_t nz = __ballot_sync(FULL, fr != 0u);
        fr_any = (nz != 0u);
        if (fr_any) {
            int l = __ffs(nz) - 1;
            uint32_t w = __shfl_sync(FULL, fr, l);
            idx = l * 32 + (__ffs(w) - 1);  // lowest rank in frontier = argmin
        }
    }

    // Stable top_k of 0/1 floats == selected node ids ascending, then unselected.
    int cnt = __popc(selO);
    int incl = cnt;
    for (int off = 1; off < 32; off <<= 1) {
        int v = __shfl_up_sync(FULL, incl, off);
        if (lane >= off) incl += v;
    }
    int excl = incl - cnt;
    int K = __shfl_sync(FULL, incl, 31);

    uint32_t s = selO; int r = 0;
    while (s) { int j = __ffs(s) - 1; s &= s - 1; g_perm[b * Nn + excl + r] = lane * 32 + j; ++r; }
    int excl_u = lane * 32 - excl;
    s = ~selO; r = 0;
    while (s) { int j = __ffs(s) - 1; s &= s - 1; g_perm[b * Nn + K + excl_u + r] = lane * 32 + j; ++r; }

    if (lane == 0) g_K[b] = K;
    for (int t = lane; t < Nn; t += 32)
        out_mask[b * Nn + t] = (t < K) ? 1.0f : 0.0f;
}

// ---------------------------------------------------------------------------
// x_p[b,k,f] = sum_{n in N(j)} x[b,n,f] + x[b,j,f], j = perm[b,k], k < K.
// k >= K rows written as zeros (no separate zero-fill pass).
__global__ void k_xp(const float* __restrict__ x, float* __restrict__ out_xp) {
    int b = blockIdx.y, k = blockIdx.x;
    int f = threadIdx.x;
    float* orow = out_xp + ((size_t)(b * Nn) + k) * Ff;
    if (k >= g_K[b]) { orow[f] = 0.0f; return; }
    int j = g_perm[b * Nn + k];
    __shared__ uint32_t sh[NW];
    if (threadIdx.x < NW) sh[threadIdx.x] = g_bits0[(b * Nn + j) * NW + threadIdx.x];
    __syncthreads();
    const float* xb = x + (size_t)b * Nn * Ff;
    float acc = xb[(size_t)j * Ff + f];
    for (int w = 0; w < NW; ++w) {
        uint32_t m = sh[w];
        while (m) {
            int n = w * 32 + __ffs(m) - 1; m &= m - 1;
            acc += xb[(size_t)n * Ff + f];
        }
    }
    orow[f] = acc;
}

// ---------------------------------------------------------------------------
// pos_p[b,k,:] = (sum_{n in N(j)} pos[n] + pos[j]) / (deg(j)+1). Warp per (b,k).
// k >= K rows written as zeros.
__global__ void k_pos(const float* __restrict__ pos, float* __restrict__ out_pos) {
    int wid  = (blockIdx.x * blockDim.x + threadIdx.x) >> 5;
    int lane = threadIdx.x & 31;
    if (wid >= Bsz * Nn) return;
    int b = wid >> 10, k = wid & (Nn - 1);
    if (k >= g_K[b]) {
        if (lane < 3) out_pos[(b * Nn + k) * 3 + lane] = 0.0f;
        return;
    }
    int j = g_perm[b * Nn + k];
    uint32_t m = g_bits0[(b * Nn + j) * NW + lane];
    const float* pb = pos + (size_t)b * Nn * 3;
    float sx = 0.f, sy = 0.f, sz = 0.f;
    int c = __popc(m);
    while (m) {
        int n = lane * 32 + __ffs(m) - 1; m &= m - 1;
        sx += pb[n * 3 + 0]; sy += pb[n * 3 + 1]; sz += pb[n * 3 + 2];
    }
    for (int off = 16; off; off >>= 1) {
        sx += __shfl_down_sync(FULL, sx, off);
        sy += __shfl_down_sync(FULL, sy, off);
        sz += __shfl_down_sync(FULL, sz, off);
        c  += __shfl_down_sync(FULL, c,  off);
    }
    if (lane == 0) {
        float deg = (float)(c + 1);
        out_pos[(b * Nn + k) * 3 + 0] = (sx + pb[j * 3 + 0]) / deg;
        out_pos[(b * Nn + k) * 3 + 1] = (sy + pb[j * 3 + 1]) / deg;
        out_pos[(b * Nn + k) * 3 + 2] = (sz + pb[j * 3 + 2]) / deg;
    }
}

// ---------------------------------------------------------------------------
// a[b,k1,k2] = popc(bits_{p1} & bits_{p2}) + A[p1,p2]  (k1,k2 < K), else 0.
// Full rows written (padding zeros included) -> no separate zero-fill pass.
__global__ void k_a(const float* __restrict__ adj, float* __restrict__ out_a) {
    int b = blockIdx.y, k1 = blockIdx.x;
    int Kc = g_K[b];
    float* orow = out_a + ((size_t)(b * Nn) + k1) * Nn;
    if (k1 >= Kc) {
        float4 z = make_float4(0.f, 0.f, 0.f, 0.f);
        ((float4*)orow)[threadIdx.x] = z;    // 256 threads x 16B = 4KB row
        return;
    }
    int p1 = g_perm[b * Nn + k1];
    __shared__ uint32_t sh[NW];
    if (threadIdx.x < NW) sh[threadIdx.x] = g_bits0[(b * Nn + p1) * NW + threadIdx.x];
    __syncthreads();
    const float* ab = adj + (size_t)(b * Nn + p1) * Nn;
    for (int k2 = threadIdx.x; k2 < Nn; k2 += blockDim.x) {
        float val = 0.0f;
        if (k2 < Kc) {
            int p2 = g_perm[b * Nn + k2];
            int c = 0;
#pragma unroll
            for (int w = 0; w < NW; ++w)
                c += __popc(sh[w] & g_bits0[(b * Nn + p2) * NW + w]);
            val = (float)c + ab[p2];
        }
        orow[k2] = val;
    }
}

// ---------------------------------------------------------------------------
extern "C" void kernel_launch(void* const* d_in, const int* in_sizes, int n_in,
                              void* d_out, int out_size) {
    const float* x     = (const float*)d_in[0];
    const float* adj   = (const float*)d_in[1];
    const float* pos   = (const float*)d_in[2];
    const float* order = (const float*)d_in[3];
    float* out = (float*)d_out;

    // adjacency bitmasks (original space): B*N*NW warps
    k_bits<<<(Bsz * Nn * NW * 32) / 256, 256>>>(adj);
    // rank nodes by order value
    k_rank<<<dim3(Bsz, 8), 128>>>(order);
    // permute bitmasks into rank space
    k_permute<<<(Bsz * Nn * 32) / 256, 256>>>();
    // 2-hop reach + fused {adj1,adj2} rows (rank space)
    k_inc<<<(Bsz * Nn * 32) / 256, 256>>>();
    // sequential selection (rank space), perm, mask
    k_select<<<Bsz, 32>>>(out + OFF_MASK);
    // pooled outputs (original space; write padding zeros inline)
    k_xp<<<dim3(Nn, Bsz), 256>>>(x, out + OFF_XP);
    k_pos<<<(Bsz * Nn * 32) / 256, 256>>>(pos, out + OFF_POS);
    k_a<<<dim3(Nn, Bsz), 256>>>(adj, out + OFF_A);
}

// round 6
// speedup vs baseline: 1.3940x; 1.2931x over previous
#include <cuda_runtime.h>
#include <cstdint>

// Problem constants
#define Bsz 4
#define Nn  1024
#define Ff  256
#define NW  32          // 1024 bits -> 32 u32 words per row
#define FULL 0xFFFFFFFFu

// Output layout (float32, tuple flattened): x_p [B,N,F], pos_p [B,N,3], a [B,N,N], mask [B,N]
#define OFF_XP   0
#define OFF_POS  (Bsz*Nn*Ff)                 // 1048576
#define OFF_A    (OFF_POS + Bsz*Nn*3)        // 1060864
#define OFF_MASK (OFF_A + Bsz*Nn*Nn)         // 5255168

// Scratch (device globals; no allocations allowed)
__device__ uint32_t g_bits0[Bsz*Nn*NW];  // A != 0, ORIGINAL node space (for pooling kernels)
__device__ uint32_t g_bitsR[Bsz*Nn*NW];  // A != 0, RANK space
__device__ uint2    g_comb [Bsz*Nn*NW];  // rank space {adj1 word, adj2 word} fused rows
__device__ int      g_nodeof[Bsz*Nn];    // nodeof[b][rank] = original node id
__device__ int      g_perm[Bsz*Nn];
__device__ int      g_K[Bsz];

// ---------------------------------------------------------------------------
// Build adjacency bitmasks (original space): one warp per 32-bit word.
__global__ void k_bits(const float* __restrict__ adj) {
    int wid  = (blockIdx.x * blockDim.x + threadIdx.x) >> 5;  // [0, B*N*NW)
    int lane = threadIdx.x & 31;
    int w    = wid & 31;
    int row  = wid >> 5;           // b*N + i
    float v  = adj[(size_t)row * Nn + w * 32 + lane];
    uint32_t bits = __ballot_sync(FULL, v != 0.0f);
    if (lane == 0) g_bits0[row * NW + w] = bits;
}

// ---------------------------------------------------------------------------
// Rank nodes by (order, index) ascending. nodeof[b][rank] = node.
// order in [0,1) -> float bits monotone as uint; key = (bits<<10)|idx.
__global__ void k_rank(const float* __restrict__ order) {
    __shared__ unsigned long long keys[Nn];
    int b = blockIdx.x, part = blockIdx.y, t = threadIdx.x;
    for (int j = t; j < Nn; j += 128)
        keys[j] = ((unsigned long long)__float_as_uint(order[b * Nn + j]) << 10) | (unsigned)j;
    __syncthreads();
    int i = part * 128 + t;
    unsigned long long ki = keys[i];
    int rk = 0;
#pragma unroll 8
    for (int j = 0; j < Nn; ++j) rk += (keys[j] < ki);
    g_nodeof[b * Nn + rk] = i;
}

// ---------------------------------------------------------------------------
// Permute bitmasks into rank space: row r = row nodeof[r], column bit j of
// word w = column nodeof[w*32+j].
__global__ void k_permute() {
    __shared__ uint32_t sm[8][NW];
    int wid  = (blockIdx.x * blockDim.x + threadIdx.x) >> 5;  // b*Nn + r
    int lane = threadIdx.x & 31;
    int wb   = (threadIdx.x >> 5) & 7;
    if (wid >= Bsz * Nn) return;
    int b = wid >> 10;
    int nid = g_nodeof[wid];
    sm[wb][lane] = g_bits0[(b * Nn + nid) * NW + lane];
    __syncwarp();
    const int4* nf = (const int4*)(g_nodeof + (b << 10) + (lane << 5));
    uint32_t out = 0;
#pragma unroll
    for (int q = 0; q < 8; ++q) {
        int4 nc = nf[q];
        out |= ((sm[wb][nc.x >> 5] >> (nc.x & 31)) & 1u) << (q * 4 + 0);
        out |= ((sm[wb][nc.y >> 5] >> (nc.y & 31)) & 1u) << (q * 4 + 1);
        out |= ((sm[wb][nc.z >> 5] >> (nc.z & 31)) & 1u) << (q * 4 + 2);
        out |= ((sm[wb][nc.w >> 5] >> (nc.w & 31)) & 1u) << (q * 4 + 3);
    }
    g_bitsR[wid * NW + lane] = out;
}

// ---------------------------------------------------------------------------
// inc_row(r) = (A^2 + A)[r] != 0, rank space. One warp per rank row.
// Stage neighbor indices in smem first, then a flat MLP-friendly load loop.
__global__ void k_inc() {
    __shared__ int16_t lists[8][96];   // max degree after symmetrization < 96
    int wid  = (blockIdx.x * blockDim.x + threadIdx.x) >> 5;
    int lane = threadIdx.x & 31;
    int wb   = (threadIdx.x >> 5) & 7;
    if (wid >= Bsz * Nn) return;
    int b = wid >> 10;
    int rowbase = wid * NW;
    uint32_t myw = g_bitsR[rowbase + lane];

    // warp prefix-sum of per-lane popcounts -> write positions
    int cnt = __popc(myw);
    int incl = cnt;
#pragma unroll
    for (int off = 1; off < 32; off <<= 1) {
        int v = __shfl_up_sync(FULL, incl, off);
        if (lane >= off) incl += v;
    }
    int base  = incl - cnt;
    int total = __shfl_sync(FULL, incl, 31);
    uint32_t m = myw; int r = 0;
    while (m) { int j = __ffs(m) - 1; m &= m - 1; lists[wb][base + r] = (int16_t)(lane * 32 + j); ++r; }
    __syncwarp();

    uint32_t acc = myw;
    const uint32_t* bb = g_bitsR + ((size_t)(b << 10)) * NW;
    int t = 0;
    for (; t + 4 <= total; t += 4) {
        int n0 = lists[wb][t], n1 = lists[wb][t+1], n2 = lists[wb][t+2], n3 = lists[wb][t+3];
        uint32_t a0 = bb[n0 * NW + lane];
        uint32_t a1 = bb[n1 * NW + lane];
        uint32_t a2 = bb[n2 * NW + lane];
        uint32_t a3 = bb[n3 * NW + lane];
        acc |= (a0 | a1) | (a2 | a3);
    }
    for (; t < total; ++t) acc |= bb[lists[wb][t] * NW + lane];
    g_comb[rowbase + lane] = make_uint2(myw, acc);
}

// ---------------------------------------------------------------------------
// Sequential greedy frontier selection, one warp per batch, rank space.
// argmin(order over mask) == lowest set bit (rank) -> REDUX.MIN of
// (lane<<5 | ctz). Frontier-empty restart handled inline (equivalent to the
// reference's idempotent repeat body with fr := av).
__global__ void __launch_bounds__(32, 1)
k_select(float* __restrict__ out_mask) {
    int b = blockIdx.x;
    int lane = threadIdx.x;
    const uint2* comb = g_comb + b * Nn * NW;
    const int* nodeof = g_nodeof + b * Nn;

    uint32_t av = FULL, selO = 0u, fr = 0u;
    int idx = 0;                           // rank 0 = global argmin

    for (;;) {
        // record selection in ORIGINAL node space (off the critical path)
        int nid = nodeof[idx];
        if (lane == (nid >> 5)) selO |= 1u << (nid & 31);

        uint32_t cur = (lane == (idx >> 5)) ? (1u << (idx & 31)) : 0u;
        uint2 rw = comb[(idx << 5) + lane];          // {adj1 word, adj2 word}
        av &= ~(rw.x | cur);
        fr = (fr | rw.y) & av;

        unsigned key = fr ? (((unsigned)lane << 5) | (unsigned)(__ffs(fr) - 1)) : FULL;
        unsigned mk = __reduce_min_sync(FULL, key);
        if (mk == FULL) {
            // frontier empty -> restart from av (or terminate if av empty)
            unsigned key2 = av ? (((unsigned)lane << 5) | (unsigned)(__ffs(av) - 1)) : FULL;
            mk = __reduce_min_sync(FULL, key2);
            if (mk == FULL) break;
            fr = av;
        }
        idx = (int)mk;
    }

    // Stable top_k of 0/1 floats == selected node ids ascending, then unselected.
    int cnt = __popc(selO);
    int incl = cnt;
#pragma unroll
    for (int off = 1; off < 32; off <<= 1) {
        int v = __shfl_up_sync(FULL, incl, off);
        if (lane >= off) incl += v;
    }
    int excl = incl - cnt;
    int K = __shfl_sync(FULL, incl, 31);

    uint32_t s = selO; int r = 0;
    while (s) { int j = __ffs(s) - 1; s &= s - 1; g_perm[b * Nn + excl + r] = lane * 32 + j; ++r; }
    int excl_u = lane * 32 - excl;
    s = ~selO; r = 0;
    while (s) { int j = __ffs(s) - 1; s &= s - 1; g_perm[b * Nn + K + excl_u + r] = lane * 32 + j; ++r; }

    if (lane == 0) g_K[b] = K;
    for (int t = lane; t < Nn; t += 32)
        out_mask[b * Nn + t] = (t < K) ? 1.0f : 0.0f;
}

// ---------------------------------------------------------------------------
// x_p[b,k,f] = sum_{n in N(j)} x[b,n,f] + x[b,j,f]; warp 0 also does the
// pos mean-pool for this (b,k). k >= K rows written as zeros.
__global__ void k_xp(const float* __restrict__ x, const float* __restrict__ pos,
                     float* __restrict__ out_xp, float* __restrict__ out_pos) {
    int b = blockIdx.y, k = blockIdx.x;
    int f = threadIdx.x;
    float* orow = out_xp + ((size_t)(b * Nn) + k) * Ff;
    if (k >= g_K[b]) {
        orow[f] = 0.0f;
        if (f < 3) out_pos[(b * Nn + k) * 3 + f] = 0.0f;
        return;
    }
    int j = g_perm[b * Nn + k];
    __shared__ uint32_t sh[NW];
    if (f < NW) sh[f] = g_bits0[(b * Nn + j) * NW + f];
    __syncthreads();
    const float* xb = x + (size_t)b * Nn * Ff;
    float acc = xb[(size_t)j * Ff + f];
    for (int w = 0; w < NW; ++w) {
        uint32_t m = sh[w];
        while (m) {
            int n = w * 32 + __ffs(m) - 1; m &= m - 1;
            acc += xb[(size_t)n * Ff + f];
        }
    }
    orow[f] = acc;

    if (f < 32) {   // warp 0: pos mean pool
        uint32_t m = sh[f];
        const float* pb = pos + (size_t)b * Nn * 3;
        float sx = 0.f, sy = 0.f, sz = 0.f;
        int c = __popc(m);
        while (m) {
            int n = f * 32 + __ffs(m) - 1; m &= m - 1;
            sx += pb[n * 3 + 0]; sy += pb[n * 3 + 1]; sz += pb[n * 3 + 2];
        }
#pragma unroll
        for (int off = 16; off; off >>= 1) {
            sx += __shfl_down_sync(FULL, sx, off);
            sy += __shfl_down_sync(FULL, sy, off);
            sz += __shfl_down_sync(FULL, sz, off);
            c  += __shfl_down_sync(FULL, c,  off);
        }
        if (f == 0) {
            float deg = (float)(c + 1);
            out_pos[(b * Nn + k) * 3 + 0] = (sx + pb[j * 3 + 0]) / deg;
            out_pos[(b * Nn + k) * 3 + 1] = (sy + pb[j * 3 + 1]) / deg;
            out_pos[(b * Nn + k) * 3 + 2] = (sz + pb[j * 3 + 2]) / deg;
        }
    }
}

// ---------------------------------------------------------------------------
// a[b,k1,k2] = popc(bits_{p1} & bits_{p2}) + A[p1,p2]  (k1,k2 < K), else 0.
// Vectorized uint4 row loads; full rows written (padding zeros inline).
__global__ void k_a(const float* __restrict__ adj, float* __restrict__ out_a) {
    int b = blockIdx.y, k1 = blockIdx.x;
    int Kc = g_K[b];
    float* orow = out_a + ((size_t)(b * Nn) + k1) * Nn;
    if (k1 >= Kc) {
        float4 z = make_float4(0.f, 0.f, 0.f, 0.f);
        ((float4*)orow)[threadIdx.x] = z;    // 256 threads x 16B = 4KB row
        return;
    }
    int p1 = g_perm[b * Nn + k1];
    __shared__ uint4 sh[NW / 4];
    if (threadIdx.x < NW / 4)
        sh[threadIdx.x] = ((const uint4*)(g_bits0 + (size_t)(b * Nn + p1) * NW))[threadIdx.x];
    __syncthreads();
    const float* ab = adj + (size_t)(b * Nn + p1) * Nn;
    for (int k2 = threadIdx.x; k2 < Nn; k2 += blockDim.x) {
        float val = 0.0f;
        if (k2 < Kc) {
            int p2 = g_perm[b * Nn + k2];
            const uint4* rp = (const uint4*)(g_bits0 + (size_t)(b * Nn + p2) * NW);
            int c = 0;
#pragma unroll
            for (int q = 0; q < NW / 4; ++q) {
                uint4 v = rp[q], s = sh[q];
                c += __popc(s.x & v.x) + __popc(s.y & v.y)
                   + __popc(s.z & v.z) + __popc(s.w & v.w);
            }
            val = (float)c + ab[p2];
        }
        orow[k2] = val;
    }
}

// ---------------------------------------------------------------------------
extern "C" void kernel_launch(void* const* d_in, const int* in_sizes, int n_in,
                              void* d_out, int out_size) {
    const float* x     = (const float*)d_in[0];
    const float* adj   = (const float*)d_in[1];
    const float* pos   = (const float*)d_in[2];
    const float* order = (const float*)d_in[3];
    float* out = (float*)d_out;

    k_bits<<<(Bsz * Nn * NW * 32) / 256, 256>>>(adj);
    k_rank<<<dim3(Bsz, 8), 128>>>(order);
    k_permute<<<(Bsz * Nn * 32) / 256, 256>>>();
    k_inc<<<(Bsz * Nn * 32) / 256, 256>>>();
    k_select<<<Bsz, 32>>>(out + OFF_MASK);
    k_xp<<<dim3(Nn, Bsz), 256>>>(x, pos, out + OFF_XP, out + OFF_POS);
    k_a<<<dim3(Nn, Bsz), 256>>>(adj, out + OFF_A);
}

// round 9
// speedup vs baseline: 1.4277x; 1.0242x over previous
#include <cuda_runtime.h>
#include <cstdint>

// Problem constants
#define Bsz 4
#define Nn  1024
#define Ff  256
#define NW  32          // 1024 bits -> 32 u32 words per row
#define FULL 0xFFFFFFFFu
#define MAXD 96         // safe bound on max degree (binomial mean ~31, sd ~5.5)

// Output layout (float32, tuple flattened): x_p [B,N,F], pos_p [B,N,3], a [B,N,N], mask [B,N]
#define OFF_XP   0
#define OFF_POS  (Bsz*Nn*Ff)                 // 1048576
#define OFF_A    (OFF_POS + Bsz*Nn*3)        // 1060864
#define OFF_MASK (OFF_A + Bsz*Nn*Nn)         // 5255168

// Scratch (device globals; no allocations allowed)
__device__ uint32_t g_bits0[Bsz*Nn*NW];  // A != 0, ORIGINAL node space
__device__ uint32_t g_bitsR[Bsz*Nn*NW];  // A != 0, RANK space
__device__ uint2    g_comb [Bsz*Nn*NW];  // rank space {adj1-with-diag word, adj2 word}
__device__ int      g_nodeof[Bsz*Nn];    // nodeof[b][rank] = original node id
__device__ int      g_perm[Bsz*Nn];
__device__ int      g_K[Bsz];

// ---------------------------------------------------------------------------
// Build adjacency bitmasks (original space): one warp per 32-bit word.
__global__ void k_bits(const float* __restrict__ adj) {
    int wid  = (blockIdx.x * blockDim.x + threadIdx.x) >> 5;  // [0, B*N*NW)
    int lane = threadIdx.x & 31;
    int w    = wid & 31;
    int row  = wid >> 5;           // b*N + i
    float v  = adj[(size_t)row * Nn + w * 32 + lane];
    uint32_t bits = __ballot_sync(FULL, v != 0.0f);
    if (lane == 0) g_bits0[row * NW + w] = bits;
}

// ---------------------------------------------------------------------------
// Rank nodes by (order, index) ascending. nodeof[b][rank] = node.
__global__ void k_rank(const float* __restrict__ order) {
    __shared__ unsigned long long keys[Nn];
    int b = blockIdx.x, part = blockIdx.y, t = threadIdx.x;
    for (int j = t; j < Nn; j += 128)
        keys[j] = ((unsigned long long)__float_as_uint(order[b * Nn + j]) << 10) | (unsigned)j;
    __syncthreads();
    int i = part * 128 + t;
    unsigned long long ki = keys[i];
    int rk = 0;
#pragma unroll 8
    for (int j = 0; j < Nn; ++j) rk += (keys[j] < ki);
    g_nodeof[b * Nn + rk] = i;
}

// ---------------------------------------------------------------------------
// Permute bitmasks into rank space.
__global__ void k_permute() {
    __shared__ uint32_t sm[8][NW];
    int wid  = (blockIdx.x * blockDim.x + threadIdx.x) >> 5;  // b*Nn + r
    int lane = threadIdx.x & 31;
    int wb   = (threadIdx.x >> 5) & 7;
    if (wid >= Bsz * Nn) return;
    int b = wid >> 10;
    int nid = g_nodeof[wid];
    sm[wb][lane] = g_bits0[(b * Nn + nid) * NW + lane];
    __syncwarp();
    const int4* nf = (const int4*)(g_nodeof + (b << 10) + (lane << 5));
    uint32_t out = 0;
#pragma unroll
    for (int q = 0; q < 8; ++q) {
        int4 nc = nf[q];
        out |= ((sm[wb][nc.x >> 5] >> (nc.x & 31)) & 1u) << (q * 4 + 0);
        out |= ((sm[wb][nc.y >> 5] >> (nc.y & 31)) & 1u) << (q * 4 + 1);
        out |= ((sm[wb][nc.z >> 5] >> (nc.z & 31)) & 1u) << (q * 4 + 2);
        out |= ((sm[wb][nc.w >> 5] >> (nc.w & 31)) & 1u) << (q * 4 + 3);
    }
    g_bitsR[wid * NW + lane] = out;
}

// ---------------------------------------------------------------------------
// comb.x = adj1 row (A row + diagonal), comb.y = adj2 row = union of neighbor
// rows | own row, all in rank space. One warp per rank row; neighbor list
// staged in smem for MLP.
__global__ void k_inc() {
    __shared__ int16_t lists[8][MAXD];
    int wid  = (blockIdx.x * blockDim.x + threadIdx.x) >> 5;
    int lane = threadIdx.x & 31;
    int wb   = (threadIdx.x >> 5) & 7;
    if (wid >= Bsz * Nn) return;
    int b = wid >> 10;
    int r = wid & (Nn - 1);        // rank of this row
    int rowbase = wid * NW;
    uint32_t myw = g_bitsR[rowbase + lane];

    int cnt = __popc(myw);
    int incl = cnt;
#pragma unroll
    for (int off = 1; off < 32; off <<= 1) {
        int v = __shfl_up_sync(FULL, incl, off);
        if (lane >= off) incl += v;
    }
    int base  = incl - cnt;
    int total = __shfl_sync(FULL, incl, 31);
    uint32_t m = myw; int rr = 0;
    while (m) { int j = __ffs(m) - 1; m &= m - 1; lists[wb][base + rr] = (int16_t)(lane * 32 + j); ++rr; }
    __syncwarp();

    uint32_t acc = myw;
    const uint32_t* bb = g_bitsR + ((size_t)(b << 10)) * NW;
    int t = 0;
    for (; t + 4 <= total; t += 4) {
        int n0 = lists[wb][t], n1 = lists[wb][t+1], n2 = lists[wb][t+2], n3 = lists[wb][t+3];
        uint32_t a0 = bb[n0 * NW + lane];
        uint32_t a1 = bb[n1 * NW + lane];
        uint32_t a2 = bb[n2 * NW + lane];
        uint32_t a3 = bb[n3 * NW + lane];
        acc |= (a0 | a1) | (a2 | a3);
    }
    for (; t < total; ++t) acc |= bb[lists[wb][t] * NW + lane];

    uint32_t selfbit = (lane == (r >> 5)) ? (1u << (r & 31)) : 0u;
    g_comb[rowbase + lane] = make_uint2(myw | selfbit, acc);
}

// ---------------------------------------------------------------------------
// Sequential greedy frontier selection, one warp per batch, rank space.
// Minimal dependent chain: LDG.64 -> LOP3 -> LOP3 -> ffs -> REDUX -> idx.
// Restart handled branchlessly with a second (parallel) REDUX over av.
__global__ void __launch_bounds__(32, 1)
k_select(float* __restrict__ out_mask) {
    int b = blockIdx.x;
    int lane = threadIdx.x;
    const uint2* comb = g_comb + b * Nn * NW;
    const int* nodeof = g_nodeof + b * Nn;

    uint32_t av = FULL, selR = 0u, fr = 0u;
    int idx = 0;                           // rank 0 = global argmin

    for (;;) {
        if (lane == (idx >> 5)) selR |= 1u << (idx & 31);
        uint2 rw = comb[(idx << 5) + lane];          // {adj1+diag, adj2}
        av &= ~rw.x;                                 // diag pre-set: removes idx too
        fr = (fr | rw.y) & av;

        unsigned k1 = fr ? (((unsigned)lane << 5) | (unsigned)(__ffs(fr) - 1)) : FULL;
        unsigned k2 = av ? (((unsigned)lane << 5) | (unsigned)(__ffs(av) - 1)) : FULL;
        unsigned m1 = __reduce_min_sync(FULL, k1);   // frontier min
        unsigned m2 = __reduce_min_sync(FULL, k2);   // available min (restart)
        bool use1 = (m1 != FULL);
        unsigned mk = use1 ? m1 : m2;
        if (mk == FULL) break;                       // av empty -> done
        if (!use1) fr = av;                          // frontier restart
        idx = (int)mk;
    }

    // Convert rank-space selection to original node ids.
    __shared__ unsigned smask[32];
    smask[lane] = 0u;
    __syncwarp();
    uint32_t s = selR;
    while (s) {
        int j = __ffs(s) - 1; s &= s - 1;
        int nid = nodeof[(lane << 5) + j];
        atomicOr(&smask[nid >> 5], 1u << (nid & 31));
    }
    __syncwarp();
    uint32_t selO = smask[lane];

    // Stable top_k of 0/1 floats == selected node ids ascending, then unselected.
    int cnt = __popc(selO);
    int incl = cnt;
#pragma unroll
    for (int off = 1; off < 32; off <<= 1) {
        int v = __shfl_up_sync(FULL, incl, off);
        if (lane >= off) incl += v;
    }
    int excl = incl - cnt;
    int K = __shfl_sync(FULL, incl, 31);

    s = selO; int r = 0;
    while (s) { int j = __ffs(s) - 1; s &= s - 1; g_perm[b * Nn + excl + r] = lane * 32 + j; ++r; }
    int excl_u = lane * 32 - excl;
    s = ~selO; r = 0;
    while (s) { int j = __ffs(s) - 1; s &= s - 1; g_perm[b * Nn + K + excl_u + r] = lane * 32 + j; ++r; }

    if (lane == 0) g_K[b] = K;
    for (int t = lane; t < Nn; t += 32)
        out_mask[b * Nn + t] = (t < K) ? 1.0f : 0.0f;
}

// ---------------------------------------------------------------------------
// Merged pooling: x_p row + pos_p row + a row for one (b,k).
// a[b,k1,k2] = popc(bits_{p1} & bits_{p2}) + bit_{p2}(bits_{p1})  -- A is 0/1,
// so the adj gather is replaced by a bit test. Padding rows zeroed inline.
__global__ void k_pool(const float* __restrict__ x, const float* __restrict__ pos,
                       float* __restrict__ out_xp, float* __restrict__ out_pos,
                       float* __restrict__ out_a) {
    int b = blockIdx.y, k = blockIdx.x;
    int t = threadIdx.x;
    int Kc = g_K[b];
    float* xrow = out_xp + ((size_t)(b * Nn) + k) * Ff;
    float* arow = out_a  + ((size_t)(b * Nn) + k) * Nn;
    if (k >= Kc) {
        xrow[t] = 0.0f;
        float4 z = make_float4(0.f, 0.f, 0.f, 0.f);
        ((float4*)arow)[t] = z;                     // 256 x 16B = 4KB row
        if (t < 3) out_pos[(b * Nn + k) * 3 + t] = 0.0f;
        return;
    }
    int j = g_perm[b * Nn + k];

    __shared__ uint32_t sh[NW];
    __shared__ int16_t nlist[MAXD];
    __shared__ int ncnt;
    if (t < 32) {
        uint32_t m = g_bits0[(b * Nn + j) * NW + t];
        sh[t] = m;
        int cnt = __popc(m);
        int incl = cnt;
#pragma unroll
        for (int off = 1; off < 32; off <<= 1) {
            int v = __shfl_up_sync(FULL, incl, off);
            if (t >= off) incl += v;
        }
        int base = incl - cnt;
        if (t == 31) ncnt = incl;
        int r = 0;
        while (m) { int jj = __ffs(m) - 1; m &= m - 1; nlist[base + r] = (int16_t)(t * 32 + jj); ++r; }
    }
    __syncthreads();

    // x add-pool: 4-wide unrolled independent loads over the neighbor list
    const float* xb = x + (size_t)b * Nn * Ff;
    float acc = xb[(size_t)j * Ff + t];
    int total = ncnt, q = 0;
    for (; q + 4 <= total; q += 4) {
        int n0 = nlist[q], n1 = nlist[q+1], n2 = nlist[q+2], n3 = nlist[q+3];
        float v0 = xb[(size_t)n0 * Ff + t];
        float v1 = xb[(size_t)n1 * Ff + t];
        float v2 = xb[(size_t)n2 * Ff + t];
        float v3 = xb[(size_t)n3 * Ff + t];
        acc += (v0 + v1) + (v2 + v3);
    }
    for (; q < total; ++q) acc += xb[(size_t)nlist[q] * Ff + t];
    xrow[t] = acc;

    // pos mean-pool (warp 0)
    if (t < 32) {
        uint32_t m = sh[t];
        const float* pb = pos + (size_t)b * Nn * 3;
        float sx = 0.f, sy = 0.f, sz = 0.f;
        int c = __popc(m);
        while (m) {
            int n = t * 32 + __ffs(m) - 1; m &= m - 1;
            sx += pb[n * 3 + 0]; sy += pb[n * 3 + 1]; sz += pb[n * 3 + 2];
        }
#pragma unroll
        for (int off = 16; off; off >>= 1) {
            sx += __shfl_down_sync(FULL, sx, off);
            sy += __shfl_down_sync(FULL, sy, off);
            sz += __shfl_down_sync(FULL, sz, off);
            c  += __shfl_down_sync(FULL, c,  off);
        }
        if (t == 0) {
            float deg = (float)(c + 1);
            out_pos[(b * Nn + k) * 3 + 0] = (sx + pb[j * 3 + 0]) / deg;
            out_pos[(b * Nn + k) * 3 + 1] = (sy + pb[j * 3 + 1]) / deg;
            out_pos[(b * Nn + k) * 3 + 2] = (sz + pb[j * 3 + 2]) / deg;
        }
    }

    // a row
    for (int k2 = t; k2 < Nn; k2 += blockDim.x) {
        float val = 0.0f;
        if (k2 < Kc) {
            int p2 = g_perm[b * Nn + k2];
            const uint4* rp = (const uint4*)(g_bits0 + (size_t)(b * Nn + p2) * NW);
            const uint4* sp = (const uint4*)sh;
            int c = 0;
#pragma unroll
            for (int qq = 0; qq < NW / 4; ++qq) {
                uint4 v = rp[qq], sv = sp[qq];
                c += __popc(sv.x & v.x) + __popc(sv.y & v.y)
                   + __popc(sv.z & v.z) + __popc(sv.w & v.w);
            }
            c += (sh[p2 >> 5] >> (p2 & 31)) & 1u;    // + A[p1,p2] (0/1 matrix)
            val = (float)c;
        }
        arow[k2] = val;
    }
}

// ---------------------------------------------------------------------------
extern "C" void kernel_launch(void* const* d_in, const int* in_sizes, int n_in,
                              void* d_out, int out_size) {
    const float* x     = (const float*)d_in[0];
    const float* adj   = (const float*)d_in[1];
    const float* pos   = (const float*)d_in[2];
    const float* order = (const float*)d_in[3];
    float* out = (float*)d_out;

    k_bits<<<(Bsz * Nn * NW * 32) / 256, 256>>>(adj);
    k_rank<<<dim3(Bsz, 8), 128>>>(order);
    k_permute<<<(Bsz * Nn * 32) / 256, 256>>>();
    k_inc<<<(Bsz * Nn * 32) / 256, 256>>>();
    k_select<<<Bsz, 32>>>(out + OFF_MASK);
    k_pool<<<dim3(Nn, Bsz), 256>>>(x, pos, out + OFF_XP, out + OFF_POS, out + OFF_A);
}